// round 7
// baseline (speedup 1.0000x reference)
#include <cuda_runtime.h>
#include <cuda_fp16.h>
#include <math.h>
#include <stdint.h>

#define D_TOT   147456
#define N_MEM   6
#define NPX     4096

// ---------------- device scratch (no allocation allowed) -------------------
__device__ float g_minmax[2];
__device__ float g_m1[D_TOT];
__device__ float g_g1[D_TOT];
__device__ float g_ws[N_MEM * D_TOT];                       // staged w, f32
__device__ __align__(16) __half g_wU[N_MEM * 16 * 128 * 128];          // wino weights
__device__ __align__(16) __half g_d[(size_t)48 * 16 * 128 * 1024];     // wino inputs

// ---------------- helpers ---------------------------------------------------
__device__ __forceinline__ uint32_t smem_u32(const void* p) {
    uint32_t a;
    asm("{ .reg .u64 t; cvta.to.shared.u64 t, %1; cvt.u32.u64 %0, t; }"
        : "=r"(a) : "l"(p));
    return a;
}
__device__ __forceinline__ void cp16(uint32_t dst, const void* src) {
    asm volatile("cp.async.cg.shared.global [%0], [%1], 16;"
                 :: "r"(dst), "l"(src) : "memory");
}
__device__ __forceinline__ void ldm4(uint32_t& r0, uint32_t& r1,
                                     uint32_t& r2, uint32_t& r3, uint32_t a) {
    asm volatile("ldmatrix.sync.aligned.m8n8.x4.shared.b16 {%0,%1,%2,%3}, [%4];"
                 : "=r"(r0), "=r"(r1), "=r"(r2), "=r"(r3) : "r"(a));
}
__device__ __forceinline__ void ldm4t(uint32_t& r0, uint32_t& r1,
                                      uint32_t& r2, uint32_t& r3, uint32_t a) {
    asm volatile("ldmatrix.sync.aligned.m8n8.x4.trans.shared.b16 {%0,%1,%2,%3}, [%4];"
                 : "=r"(r0), "=r"(r1), "=r"(r2), "=r"(r3) : "r"(a));
}
__device__ __forceinline__ void mma16(float4& d, const uint32_t* a,
                                      uint32_t b0, uint32_t b1) {
    asm volatile(
        "mma.sync.aligned.m16n8k16.row.col.f32.f16.f16.f32 "
        "{%0,%1,%2,%3},{%4,%5,%6,%7},{%8,%9},{%0,%1,%2,%3};"
        : "+f"(d.x), "+f"(d.y), "+f"(d.z), "+f"(d.w)
        : "r"(a[0]), "r"(a[1]), "r"(a[2]), "r"(a[3]), "r"(b0), "r"(b1));
}

// ---------------------------------------------------------------------------
// Stage 0: global max/min of U
// ---------------------------------------------------------------------------
__global__ void init_minmax_kernel() { g_minmax[0] = -INFINITY; g_minmax[1] = INFINITY; }

__device__ __forceinline__ void atomicMaxF(float* a, float v) {
    if (v >= 0.f) atomicMax((int*)a, __float_as_int(v));
    else          atomicMin((unsigned int*)a, __float_as_uint(v));
}
__device__ __forceinline__ void atomicMinF(float* a, float v) {
    if (v >= 0.f) atomicMin((int*)a, __float_as_int(v));
    else          atomicMax((unsigned int*)a, __float_as_uint(v));
}

__global__ void reduce_minmax_kernel(const float* __restrict__ U, int n) {
    float mx = -INFINITY, mn = INFINITY;
    for (int i = blockIdx.x * blockDim.x + threadIdx.x; i < n; i += gridDim.x * blockDim.x) {
        float v = U[i]; mx = fmaxf(mx, v); mn = fminf(mn, v);
    }
#pragma unroll
    for (int o = 16; o; o >>= 1) {
        mx = fmaxf(mx, __shfl_xor_sync(0xffffffffu, mx, o));
        mn = fminf(mn, __shfl_xor_sync(0xffffffffu, mn, o));
    }
    if ((threadIdx.x & 31) == 0) { atomicMaxF(&g_minmax[0], mx); atomicMinF(&g_minmax[1], mn); }
}

// ---------------------------------------------------------------------------
// Stage 1: m1 + shared gate g1
// ---------------------------------------------------------------------------
__device__ __forceinline__ float stable_sigmoid(float x) {
    if (x >= 0.f) return 1.f / (1.f + __expf(-x));
    float e = __expf(x); return e / (1.f + e);
}
__device__ __forceinline__ float gatef(float uu, float b) {
    float g  = __logf(uu / (1.f - uu));
    float bs = stable_sigmoid(g + b);
    float t  = __fadd_rn(__fmul_rn(bs, 1.4f), -0.2f);
    return fminf(fmaxf(t, 0.f), 1.f);
}

__global__ void compute_m1_kernel(const float* __restrict__ U,
                                  const float* __restrict__ bp,
                                  const float* __restrict__ uu) {
    int d = blockIdx.x * blockDim.x + threadIdx.x;
    if (d >= D_TOT) return;
    float s1 = (g_minmax[0] - g_minmax[1]) / 3.0f;
    float s = 0.f;
#pragma unroll
    for (int nn = 0; nn < N_MEM; nn++) s += s1 * rintf(U[nn * D_TOT + d] / s1);
    g_m1[d] = s * (1.0f / 6.0f);
    g_g1[d] = gatef(uu[6 * D_TOT + d], bp[6 * D_TOT + d]);
}

// ---------------------------------------------------------------------------
// Stage 2: gates + residual quantization -> staged fp32 weights g_ws[n][d]
// ---------------------------------------------------------------------------
__global__ void compute_w_kernel(const float* __restrict__ U,
                                 const float* __restrict__ bp,
                                 const float* __restrict__ uu) {
    int idx = blockIdx.x * blockDim.x + threadIdx.x;
    if (idx >= N_MEM * D_TOT) return;
    int d  = idx % D_TOT;

    float s1 = (g_minmax[0] - g_minmax[1]) / 3.0f;
    float s2 = s1 / 5.0f;

    float Uv = U[idx];
    float v1 = s1 * rintf(Uv / s1);
    float v2 = s2 * rintf((Uv - g_m1[d]) / s2);

    float g0 = gatef(uu[idx], bp[idx]);
    g_ws[idx] = v1 * g0 + ((g0 > 0.f) ? v2 * g_g1[d] : 0.f);
}

// ---------------------------------------------------------------------------
// Stage 3: weight Winograd transform u = G g G^T -> g_wU[n][comp][oc][ic] fp16
// ---------------------------------------------------------------------------
__global__ void wino_w_kernel() {
    int idx = blockIdx.x * blockDim.x + threadIdx.x;
    if (idx >= N_MEM * 128 * 128) return;
    int n  = idx >> 14;
    int r  = idx & 16383;
    int oc = r >> 7, ic = r & 127;

    const float* w = g_ws + (size_t)n * D_TOT + oc * 1152 + ic * 9;
    float g[9];
#pragma unroll
    for (int i = 0; i < 9; i++) g[i] = w[i];

    float T[4][3];
#pragma unroll
    for (int c = 0; c < 3; c++) {
        T[0][c] = g[c];
        T[1][c] = 0.5f * (g[c] + g[3 + c] + g[6 + c]);
        T[2][c] = 0.5f * (g[c] - g[3 + c] + g[6 + c]);
        T[3][c] = g[6 + c];
    }
    __half* up = g_wU + (((size_t)n * 16) * 128 + oc) * 128 + ic;
#pragma unroll
    for (int rr = 0; rr < 4; rr++) {
        float u0 = T[rr][0];
        float u1 = 0.5f * (T[rr][0] + T[rr][1] + T[rr][2]);
        float u2 = 0.5f * (T[rr][0] - T[rr][1] + T[rr][2]);
        float u3 = T[rr][2];
        up[(size_t)(rr * 4 + 0) * 16384] = __float2half_rn(u0);
        up[(size_t)(rr * 4 + 1) * 16384] = __float2half_rn(u1);
        up[(size_t)(rr * 4 + 2) * 16384] = __float2half_rn(u2);
        up[(size_t)(rr * 4 + 3) * 16384] = __float2half_rn(u3);
    }
}

// ---------------------------------------------------------------------------
// Stage 4: input Winograd transform d = B^T X B -> g_d[s][comp][ic][tile] fp16
//   tile = ty*32 + tx, 4x4 patch at rows 2ty-1.., cols 2tx-1.. (pad 1)
// ---------------------------------------------------------------------------
__global__ void wino_in_kernel(const float* __restrict__ x) {
    int tx = threadIdx.x;
    int ty = blockIdx.x;
    int ic = blockIdx.y * 8 + threadIdx.y;
    int s  = blockIdx.z;

    const float* xs = x + ((size_t)s * 128 + ic) * NPX;
    float X[4][4];
    int gy0 = 2 * ty - 1, gx0 = 2 * tx - 1;
#pragma unroll
    for (int r = 0; r < 4; r++) {
        int gy = gy0 + r;
        bool yok = (unsigned)gy < 64u;
#pragma unroll
        for (int c = 0; c < 4; c++) {
            int gx = gx0 + c;
            X[r][c] = (yok && (unsigned)gx < 64u) ? xs[gy * 64 + gx] : 0.f;
        }
    }
    float T[4][4];
#pragma unroll
    for (int c = 0; c < 4; c++) {
        T[0][c] = X[0][c] - X[2][c];
        T[1][c] = X[1][c] + X[2][c];
        T[2][c] = X[2][c] - X[1][c];
        T[3][c] = X[1][c] - X[3][c];
    }
    __half* dp = g_d + (((size_t)s * 16) * 128 + ic) * 1024 + ty * 32 + tx;
#pragma unroll
    for (int r = 0; r < 4; r++) {
        float d0 = T[r][0] - T[r][2];
        float d1 = T[r][1] + T[r][2];
        float d2 = T[r][2] - T[r][1];
        float d3 = T[r][1] - T[r][3];
        dp[(size_t)(r * 4 + 0) * 131072] = __float2half_rn(d0);
        dp[(size_t)(r * 4 + 1) * 131072] = __float2half_rn(d1);
        dp[(size_t)(r * 4 + 2) * 131072] = __float2half_rn(d2);
        dp[(size_t)(r * 4 + 3) * 131072] = __float2half_rn(d3);
    }
}

// ---------------------------------------------------------------------------
// Stage 5: Winograd GEMM + fused output transform.
//   CTA: 64 oc x 32 tiles x 16 comps (warp = comp), 512 threads.
//   K=128 in 4 chunks of 32, double-buffered cp.async, XOR-swizzled smem.
//   smem chunk: A 1024 rows x 64B (65536) + B 512 rows x 64B (32768) = 98304 B.
// ---------------------------------------------------------------------------
#define CH_BYTES 98304
#define SM_BYTES (2 * CH_BYTES)            // 196608

__device__ __forceinline__ void wg_issue(int kc, int buf, uint32_t sbase, int tid,
                                         const __half* Asrc, const __half* Bsrc) {
    uint32_t bb = sbase + (uint32_t)buf * CH_BYTES;
#pragma unroll
    for (int i = 0; i < 8; i++) {                       // A: [comp][oc][k32]
        int id  = tid + i * 512;
        int row = id >> 2, j = id & 3;
        int comp = row >> 6, oc = row & 63;
        const __half* src = Asrc + (size_t)comp * 16384 + oc * 128 + kc * 32 + j * 8;
        cp16(bb + row * 64 + ((j ^ ((row >> 1) & 3)) << 4), src);
    }
#pragma unroll
    for (int i = 0; i < 4; i++) {                       // B: [comp][k32][n32]
        int id  = tid + i * 512;
        int row = id >> 2, j = id & 3;
        int comp = row >> 5, k = row & 31;
        const __half* src = Bsrc + (size_t)comp * 131072 + (kc * 32 + k) * 1024 + j * 8;
        cp16(bb + 65536 + row * 64 + ((j ^ ((row >> 1) & 3)) << 4), src);
    }
    asm volatile("cp.async.commit_group;" ::: "memory");
}

__global__ __launch_bounds__(512, 1)
void wino_gemm_kernel(float* __restrict__ out) {
    extern __shared__ __half smh[];
    uint32_t sbase = smem_u32(smh);

    const int tid = threadIdx.x;
    const int tg  = blockIdx.x;          // tile row ty (32 tiles across)
    const int ocg = blockIdx.y;          // oc half
    const int s   = blockIdx.z;
    const int n   = s % N_MEM;
    const int wid = tid >> 5;            // comp 0..15
    const int l   = tid & 31;

    const __half* Asrc = g_wU + ((size_t)n * 16) * 16384 + ocg * 64 * 128;
    const __half* Bsrc = g_d + (size_t)s * 16 * 131072 + tg * 32;

    float4 acc[4][4];
#pragma unroll
    for (int i = 0; i < 4; i++)
#pragma unroll
        for (int j = 0; j < 4; j++) acc[i][j] = make_float4(0.f, 0.f, 0.f, 0.f);

    wg_issue(0, 0, sbase, tid, Asrc, Bsrc);
    wg_issue(1, 1, sbase, tid, Asrc, Bsrc);

#pragma unroll
    for (int c = 0; c < 4; c++) {
        if (c < 3) asm volatile("cp.async.wait_group 1;" ::: "memory");
        else       asm volatile("cp.async.wait_group 0;" ::: "memory");
        __syncthreads();

        uint32_t bb = sbase + (uint32_t)(c & 1) * CH_BYTES;
#pragma unroll
        for (int kf = 0; kf < 2; kf++) {
            uint32_t a[4][4];
#pragma unroll
            for (int mt = 0; mt < 4; mt++) {
                int row  = wid * 64 + mt * 16 + (l & 15);
                int slot = (kf * 2 + ((l >> 4) & 1)) ^ ((row >> 1) & 3);
                ldm4(a[mt][0], a[mt][1], a[mt][2], a[mt][3], bb + row * 64 + slot * 16);
            }
#pragma unroll
            for (int nf = 0; nf < 2; nf++) {
                int row  = wid * 32 + kf * 16 + (l & 15);
                int slot = (nf * 2 + ((l >> 4) & 1)) ^ ((row >> 1) & 3);
                uint32_t b0, b1, b2, b3;
                ldm4t(b0, b1, b2, b3, bb + 65536 + row * 64 + slot * 16);
#pragma unroll
                for (int mt = 0; mt < 4; mt++) {
                    mma16(acc[mt][nf * 2],     a[mt], b0, b1);
                    mma16(acc[mt][nf * 2 + 1], a[mt], b2, b3);
                }
            }
        }
        __syncthreads();
        if (c + 2 < 4)
            wg_issue(c + 2, c & 1, sbase, tid, Asrc, Bsrc);
    }

    // ---- fused output transform: stage comps in smem, combine, store ----
    float* smf = (float*)smh;            // 16 x 64 x 32 floats = 128 KB
#pragma unroll
    for (int mt = 0; mt < 4; mt++)
#pragma unroll
        for (int nb = 0; nb < 4; nb++) {
            int ocl  = mt * 16 + (l >> 2);
            int tile = nb * 8 + (l & 3) * 2;
            float4 d = acc[mt][nb];
            *(float2*)&smf[wid * 2048 + ocl * 32 + tile]       = make_float2(d.x, d.y);
            *(float2*)&smf[wid * 2048 + (ocl + 8) * 32 + tile] = make_float2(d.z, d.w);
        }
    __syncthreads();

#pragma unroll
    for (int k = 0; k < 4; k++) {
        int p    = tid + k * 512;
        int ocl  = p >> 5;
        int tile = p & 31;
        float m[16];
#pragma unroll
        for (int c = 0; c < 16; c++) m[c] = smf[c * 2048 + ocl * 32 + tile];

        float p0[4], p1[4];
#pragma unroll
        for (int i = 0; i < 4; i++) {
            p0[i] = m[i * 4 + 0] + m[i * 4 + 1] + m[i * 4 + 2];
            p1[i] = m[i * 4 + 1] - m[i * 4 + 2] - m[i * 4 + 3];
        }
        float y00 = p0[0] + p0[1] + p0[2];
        float y01 = p1[0] + p1[1] + p1[2];
        float y10 = p0[1] - p0[2] - p0[3];
        float y11 = p1[1] - p1[2] - p1[3];

        float* op = out + (((size_t)s * 128 + ocg * 64 + ocl) * 64 + 2 * tg) * 64 + 2 * tile;
        *(float2*)op        = make_float2(y00, y01);
        *(float2*)(op + 64) = make_float2(y10, y11);
    }
}

// ---------------------------------------------------------------------------
extern "C" void kernel_launch(void* const* d_in, const int* in_sizes, int n_in,
                              void* d_out, int out_size) {
    const float* x  = (const float*)d_in[0];   // (48,128,64,64)
    const float* U  = (const float*)d_in[1];   // (6, 147456)
    const float* bp = (const float*)d_in[2];   // (7, 147456)
    const float* u  = (const float*)d_in[3];   // (7, 147456)
    float* out = (float*)d_out;                // (48,128,64,64)

    cudaFuncSetAttribute(wino_gemm_kernel, cudaFuncAttributeMaxDynamicSharedMemorySize, SM_BYTES);

    init_minmax_kernel<<<1, 1>>>();
    reduce_minmax_kernel<<<432, 256>>>(U, N_MEM * D_TOT);
    compute_m1_kernel<<<(D_TOT + 255) / 256, 256>>>(U, bp, u);
    compute_w_kernel<<<(N_MEM * D_TOT + 255) / 256, 256>>>(U, bp, u);
    wino_w_kernel<<<(N_MEM * 128 * 128 + 255) / 256, 256>>>();
    wino_in_kernel<<<dim3(32, 16, 48), dim3(32, 8)>>>(x);

    wino_gemm_kernel<<<dim3(32, 2, 48), 512, SM_BYTES>>>(out);
}